// round 1
// baseline (speedup 1.0000x reference)
#include <cuda_runtime.h>

#define BB   256
#define TT   2048
#define INP  29
#define HH   64
#define GG   192   // 3*H
#define OUTD 11
#define RR   4     // batch rows per CTA

// Scratch (device globals — no allocation allowed)
__device__ float g_out0[(size_t)BB * TT * 2 * HH];  // [B][T][128] layer-0 bi output
__device__ float g_hT[BB * 2 * HH];                 // [B][128] final states of layer 1

__device__ __forceinline__ float sigf(float v) {
    v = fminf(fmaxf(v, -30.f), 30.f);
    return 1.f / (1.f + __expf(-v));
}
__device__ __forceinline__ float tanh_f(float v) {
    v = fminf(fmaxf(v, -15.f), 15.f);
    float e = __expf(-2.f * v);
    return (1.f - e) / (1.f + e);
}

// ---------------------------------------------------------------------------
// Layer 0: fused input GEMV (K=29) + hidden recurrence. 192 threads, 4 rows.
// Thread j owns gate element j; holds Whh row (64 regs) + Wih row (32 regs).
// ---------------------------------------------------------------------------
__global__ void __launch_bounds__(192, 1) gru_layer0(
    const float* __restrict__ x,
    const float* __restrict__ Wih_f, const float* __restrict__ Whh_f,
    const float* __restrict__ bih_f, const float* __restrict__ bhh_f,
    const float* __restrict__ Wih_b, const float* __restrict__ Whh_b,
    const float* __restrict__ bih_b, const float* __restrict__ bhh_b)
{
    const int dir = blockIdx.y;
    const int b0  = blockIdx.x * RR;
    const int j   = threadIdx.x;

    const float* Wih = dir ? Wih_b : Wih_f;
    const float* Whh = dir ? Whh_b : Whh_f;
    const float* bih = dir ? bih_b : bih_f;
    const float* bhh = dir ? bhh_b : bhh_f;

    float wh[HH];
#pragma unroll
    for (int c = 0; c < HH / 4; c++) {
        float4 v = *(const float4*)&Whh[j * HH + c * 4];
        wh[c * 4 + 0] = v.x; wh[c * 4 + 1] = v.y;
        wh[c * 4 + 2] = v.z; wh[c * 4 + 3] = v.w;
    }
    float wi[32];
#pragma unroll
    for (int i = 0; i < 32; i++) wi[i] = (i < INP) ? Wih[j * INP + i] : 0.f;
    const float bh = bhh[j];
    const float bi = bih[j];

    __shared__ float h_sm[RR][HH];
    __shared__ float x_sm[2][RR][32];   // padded 29 -> 32
    __shared__ float A_sm[RR][GG];      // hidden dot + bhh
    __shared__ float Bx_sm[RR][GG];     // input  dot + bih

    for (int e = j; e < RR * HH; e += 192) h_sm[e >> 6][e & 63] = 0.f;
    for (int e = j; e < 2 * RR * 32; e += 192) ((float*)x_sm)[e] = 0.f;
    __syncthreads();
    {   // preload first step's x
        const int t0 = dir ? (TT - 1) : 0;
        if (j < RR * INP) {
            int r = j / INP, i = j % INP;
            x_sm[0][r][i] = x[((size_t)(b0 + r) * TT + t0) * INP + i];
        }
    }
    __syncthreads();

    const int tstep = dir ? -1 : 1;
    int t = dir ? (TT - 1) : 0;
    const int pr = j / INP, pi = j % INP;

    for (int s = 0; s < TT; s++, t += tstep) {
        const int cur = s & 1;
        // prefetch next step's x into registers (hide DRAM latency behind GEMV)
        float pf = 0.f;
        const bool dopf = (s + 1 < TT) && (j < RR * INP);
        if (dopf) pf = x[((size_t)(b0 + pr) * TT + (t + tstep)) * INP + pi];

        float accA[RR], accB[RR];
#pragma unroll
        for (int r = 0; r < RR; r++) { accA[r] = bh; accB[r] = bi; }

#pragma unroll
        for (int c = 0; c < HH / 4; c++) {
#pragma unroll
            for (int r = 0; r < RR; r++) {
                float4 hv = *(const float4*)&h_sm[r][c * 4];
                accA[r] += wh[c * 4 + 0] * hv.x;
                accA[r] += wh[c * 4 + 1] * hv.y;
                accA[r] += wh[c * 4 + 2] * hv.z;
                accA[r] += wh[c * 4 + 3] * hv.w;
            }
        }
#pragma unroll
        for (int c = 0; c < 8; c++) {
#pragma unroll
            for (int r = 0; r < RR; r++) {
                float4 xv = *(const float4*)&x_sm[cur][r][c * 4];
                accB[r] += wi[c * 4 + 0] * xv.x;
                accB[r] += wi[c * 4 + 1] * xv.y;
                accB[r] += wi[c * 4 + 2] * xv.z;
                accB[r] += wi[c * 4 + 3] * xv.w;
            }
        }
#pragma unroll
        for (int r = 0; r < RR; r++) { A_sm[r][j] = accA[r]; Bx_sm[r][j] = accB[r]; }
        __syncthreads();

        // gate math + state update + output write
        for (int e = j; e < RR * HH; e += 192) {
            int r = e >> 6, k = e & 63;
            float rg = sigf(A_sm[r][k]      + Bx_sm[r][k]);
            float zg = sigf(A_sm[r][64 + k] + Bx_sm[r][64 + k]);
            float ng = tanh_f(Bx_sm[r][128 + k] + rg * A_sm[r][128 + k]);
            float hv = h_sm[r][k];
            float hn = (1.f - zg) * ng + zg * hv;
            h_sm[r][k] = hn;
            g_out0[(((size_t)(b0 + r) * TT + t) << 7) + dir * HH + k] = hn;
        }
        if (dopf) x_sm[cur ^ 1][pr][pi] = pf;
        __syncthreads();
    }
}

// ---------------------------------------------------------------------------
// Layer 1: input GEMV (K=128) + hidden recurrence, final states only.
// 576 threads: gate j = tid%192, k-segment = tid/192 (0:hidden, 1/2: input).
// Each thread holds a 64-wide weight slice in registers; smem partial reduce.
// ---------------------------------------------------------------------------
#define BD1 576
__global__ void __launch_bounds__(BD1, 1) gru_layer1(
    const float* __restrict__ Wih_f, const float* __restrict__ Whh_f,
    const float* __restrict__ bih_f, const float* __restrict__ bhh_f,
    const float* __restrict__ Wih_b, const float* __restrict__ Whh_b,
    const float* __restrict__ bih_b, const float* __restrict__ bhh_b)
{
    const int dir  = blockIdx.y;
    const int b0   = blockIdx.x * RR;
    const int tid  = threadIdx.x;
    const int j    = tid % GG;
    const int kseg = tid / GG;

    const float* Wih = dir ? Wih_b : Wih_f;
    const float* Whh = dir ? Whh_b : Whh_f;
    const float* bih = dir ? bih_b : bih_f;
    const float* bhh = dir ? bhh_b : bhh_f;

    float w[HH];
    if (kseg == 0) {
#pragma unroll
        for (int c = 0; c < HH / 4; c++) {
            float4 v = *(const float4*)&Whh[j * HH + c * 4];
            w[c * 4] = v.x; w[c * 4 + 1] = v.y; w[c * 4 + 2] = v.z; w[c * 4 + 3] = v.w;
        }
    } else {
        const int off = (kseg - 1) * HH;
#pragma unroll
        for (int c = 0; c < HH / 4; c++) {
            float4 v = *(const float4*)&Wih[j * (2 * HH) + off + c * 4];
            w[c * 4] = v.x; w[c * 4 + 1] = v.y; w[c * 4 + 2] = v.z; w[c * 4 + 3] = v.w;
        }
    }
    const float bias = (kseg == 0) ? bhh[j] : ((kseg == 1) ? bih[j] : 0.f);

    __shared__ float h_sm[RR][HH];
    __shared__ float x_sm[2][RR][2 * HH];
    __shared__ float P_sm[3][RR][GG];   // partial sums per k-segment

    for (int e = tid; e < RR * HH; e += BD1) h_sm[e >> 6][e & 63] = 0.f;
    {
        const int t0 = dir ? (TT - 1) : 0;
        if (tid < RR * 2 * HH) {
            int r = tid >> 7, i = tid & 127;
            x_sm[0][r][i] = g_out0[(((size_t)(b0 + r) * TT + t0) << 7) + i];
        }
    }
    __syncthreads();

    const int tstep = dir ? -1 : 1;
    int t = dir ? (TT - 1) : 0;
    const int pr = tid >> 7, pi = tid & 127;

    for (int s = 0; s < TT; s++, t += tstep) {
        const int cur = s & 1;
        float pf = 0.f;
        const bool dopf = (s + 1 < TT) && (tid < RR * 2 * HH);
        if (dopf) pf = g_out0[(((size_t)(b0 + pr) * TT + (t + tstep)) << 7) + pi];

        float acc[RR];
#pragma unroll
        for (int r = 0; r < RR; r++) acc[r] = bias;

        // source vector for this thread's k-segment (warp-uniform branch)
        const float* src0 = (kseg == 0) ? &h_sm[0][0] : &x_sm[cur][0][(kseg - 1) * HH];
        const int srcstride = (kseg == 0) ? HH : (2 * HH);
#pragma unroll
        for (int c = 0; c < HH / 4; c++) {
#pragma unroll
            for (int r = 0; r < RR; r++) {
                float4 v = *(const float4*)&src0[r * srcstride + c * 4];
                acc[r] += w[c * 4 + 0] * v.x;
                acc[r] += w[c * 4 + 1] * v.y;
                acc[r] += w[c * 4 + 2] * v.z;
                acc[r] += w[c * 4 + 3] * v.w;
            }
        }
#pragma unroll
        for (int r = 0; r < RR; r++) P_sm[kseg][r][j] = acc[r];
        __syncthreads();

        if (tid < RR * HH) {
            int r = tid >> 6, k = tid & 63;
            float hr = P_sm[0][r][k];
            float xr = P_sm[1][r][k]       + P_sm[2][r][k];
            float hz = P_sm[0][r][64 + k];
            float xz = P_sm[1][r][64 + k]  + P_sm[2][r][64 + k];
            float hn = P_sm[0][r][128 + k];
            float xn = P_sm[1][r][128 + k] + P_sm[2][r][128 + k];
            float rg = sigf(xr + hr);
            float zg = sigf(xz + hz);
            float ng = tanh_f(xn + rg * hn);
            h_sm[r][k] = (1.f - zg) * ng + zg * h_sm[r][k];
        }
        if (dopf) x_sm[cur ^ 1][pr][pi] = pf;
        __syncthreads();
    }

    if (tid < RR * HH) {
        int r = tid >> 6, k = tid & 63;
        g_hT[(b0 + r) * (2 * HH) + dir * HH + k] = h_sm[r][k];
    }
}

// ---------------------------------------------------------------------------
// Head: LayerNorm(128) -> Linear(128->64)+ReLU -> Linear(64->11)
// ---------------------------------------------------------------------------
__global__ void __launch_bounds__(128, 4) head_kernel(
    const float* __restrict__ ln_g, const float* __restrict__ ln_b,
    const float* __restrict__ W1, const float* __restrict__ b1,
    const float* __restrict__ W2, const float* __restrict__ b2,
    float* __restrict__ out)
{
    const int b = blockIdx.x;
    const int tid = threadIdx.x;
    const int lane = tid & 31, wid = tid >> 5;

    __shared__ float y_sm[128];
    __shared__ float h_sm[HH];
    __shared__ float r1[4], r2[4];
    __shared__ float stats[2];

    float e = g_hT[b * 128 + tid];
    float s1 = e, s2 = e * e;
#pragma unroll
    for (int o = 16; o; o >>= 1) {
        s1 += __shfl_down_sync(0xffffffffu, s1, o);
        s2 += __shfl_down_sync(0xffffffffu, s2, o);
    }
    if (lane == 0) { r1[wid] = s1; r2[wid] = s2; }
    __syncthreads();
    if (tid == 0) {
        float a = r1[0] + r1[1] + r1[2] + r1[3];
        float c = r2[0] + r2[1] + r2[2] + r2[3];
        float mu = a * (1.f / 128.f);
        float var = c * (1.f / 128.f) - mu * mu;
        stats[0] = mu;
        stats[1] = rsqrtf(var + 1e-5f);
    }
    __syncthreads();
    y_sm[tid] = (e - stats[0]) * stats[1] * ln_g[tid] + ln_b[tid];
    __syncthreads();

    if (tid < HH) {
        float acc = b1[tid];
#pragma unroll
        for (int k = 0; k < 128; k++) acc += W1[tid * 128 + k] * y_sm[k];
        h_sm[tid] = fmaxf(acc, 0.f);
    }
    __syncthreads();
    if (tid < OUTD) {
        float acc = b2[tid];
#pragma unroll
        for (int k = 0; k < HH; k++) acc += W2[tid * HH + k] * h_sm[k];
        out[b * OUTD + tid] = acc;
    }
}

// ---------------------------------------------------------------------------
extern "C" void kernel_launch(void* const* d_in, const int* in_sizes, int n_in,
                              void* d_out, int out_size) {
    (void)in_sizes; (void)n_in; (void)out_size;
    const float* x     = (const float*)d_in[0];
    const float* Wih00 = (const float*)d_in[1];
    const float* Whh00 = (const float*)d_in[2];
    const float* bih00 = (const float*)d_in[3];
    const float* bhh00 = (const float*)d_in[4];
    const float* Wih01 = (const float*)d_in[5];
    const float* Whh01 = (const float*)d_in[6];
    const float* bih01 = (const float*)d_in[7];
    const float* bhh01 = (const float*)d_in[8];
    const float* Wih10 = (const float*)d_in[9];
    const float* Whh10 = (const float*)d_in[10];
    const float* bih10 = (const float*)d_in[11];
    const float* bhh10 = (const float*)d_in[12];
    const float* Wih11 = (const float*)d_in[13];
    const float* Whh11 = (const float*)d_in[14];
    const float* bih11 = (const float*)d_in[15];
    const float* bhh11 = (const float*)d_in[16];
    const float* ln_g  = (const float*)d_in[17];
    const float* ln_b  = (const float*)d_in[18];
    const float* W1    = (const float*)d_in[19];
    const float* b1    = (const float*)d_in[20];
    const float* W2    = (const float*)d_in[21];
    const float* b2    = (const float*)d_in[22];
    float* out = (float*)d_out;

    dim3 g0(BB / RR, 2);
    gru_layer0<<<g0, 192>>>(x, Wih00, Whh00, bih00, bhh00,
                            Wih01, Whh01, bih01, bhh01);
    dim3 g1(BB / RR, 2);
    gru_layer1<<<g1, BD1>>>(Wih10, Whh10, bih10, bhh10,
                            Wih11, Whh11, bih11, bhh11);
    head_kernel<<<BB, 128>>>(ln_g, ln_b, W1, b1, W2, b2, out);
}

// round 2
// speedup vs baseline: 1.2827x; 1.2827x over previous
#include <cuda_runtime.h>

#define BB   256
#define TT   2048
#define INP  29
#define HH   64
#define GG   192   // 3*H
#define NN2  384   // both directions
#define OUTD 11
#define RR   4     // batch rows per recurrence CTA
#define MT   ((size_t)BB * TT)

// Scratch (device globals — no allocation allowed)
__device__ float g_out0[(size_t)BB * TT * 2 * HH];   // [B*T][128] layer-0 bi output
__device__ float g_gx0[(size_t)BB * TT * NN2];       // [B*T][384] layer-0 input gates (both dirs)
__device__ float g_gx1[(size_t)BB * TT * NN2];       // [B*T][384] layer-1 input gates
__device__ float g_hT[BB * 2 * HH];                  // [B][128] final states of layer 1

// ---------------------------------------------------------------------------
// f32x2 packed helpers (Blackwell FFMA2 — 2x fp32 FMA throughput)
// ---------------------------------------------------------------------------
__device__ __forceinline__ void fma2(unsigned long long& acc,
                                     unsigned long long a, unsigned long long b) {
    asm("fma.rn.f32x2 %0, %1, %2, %0;" : "+l"(acc) : "l"(a), "l"(b));
}
__device__ __forceinline__ unsigned long long dup2(float f) {
    unsigned long long d;
    unsigned int u = __float_as_uint(f);
    asm("mov.b64 %0, {%1, %1};" : "=l"(d) : "r"(u));
    return d;
}
__device__ __forceinline__ float2 unpk(unsigned long long v) {
    unsigned int a, b;
    asm("mov.b64 {%0, %1}, %2;" : "=r"(a), "=r"(b) : "l"(v));
    float2 r; r.x = __uint_as_float(a); r.y = __uint_as_float(b);
    return r;
}

__device__ __forceinline__ float sigf(float v) {
    v = fminf(fmaxf(v, -30.f), 30.f);
    return 1.f / (1.f + __expf(-v));
}
__device__ __forceinline__ float tanh_f(float v) {
    v = fminf(fmaxf(v, -15.f), 15.f);
    float e = __expf(-2.f * v);
    return (1.f - e) / (1.f + e);
}

// ---------------------------------------------------------------------------
// Input-gate GEMM: gx[m][384] = A[m][KREAL] @ Wcat[384][KREAL]^T + bcat
// CTA tile: 128 M x 64 N, 256 threads, thread tile 8M x 4N via f32x2 M-pairs.
// smem: xT[KK][128] (transposed A tile), ws[KK][64] (transposed W tile).
// ---------------------------------------------------------------------------
template<int KK, int KREAL>
__global__ void __launch_bounds__(256, 2) gemm_gx_kernel(
    const float* __restrict__ A, int lda,
    const float* __restrict__ Wf, const float* __restrict__ Wb,
    const float* __restrict__ bf, const float* __restrict__ bb,
    float* __restrict__ gx)
{
    extern __shared__ float sm[];
    float* xT = sm;               // [KK][128]
    float* ws = sm + KK * 128;    // [KK][64]

    const int tid = threadIdx.x;
    const int m0g = blockIdx.x * 128;
    const int n0g = blockIdx.y * 64;

    // ---- load A tile transposed: lanes span m (conflict-free STS) ----
    if (KK == KREAL) {
#pragma unroll
        for (int it = 0; it < 128 * (KK / 4) / 256; it++) {
            int idx = tid + it * 256;
            int m = idx % 128, k4 = idx / 128;
            float4 v = *(const float4*)&A[(size_t)(m0g + m) * lda + k4 * 4];
            xT[(k4 * 4 + 0) * 128 + m] = v.x;
            xT[(k4 * 4 + 1) * 128 + m] = v.y;
            xT[(k4 * 4 + 2) * 128 + m] = v.z;
            xT[(k4 * 4 + 3) * 128 + m] = v.w;
        }
    } else {
#pragma unroll
        for (int it = 0; it < 128 * KK / 256; it++) {
            int idx = tid + it * 256;
            int m = idx % 128, k = idx / 128;
            xT[k * 128 + m] = (k < KREAL) ? A[(size_t)(m0g + m) * lda + k] : 0.f;
        }
    }
    // ---- load W tile transposed: ws[k][n], lanes span n (conflict-free) ----
#pragma unroll
    for (int it = 0; it < KK * 64 / 256; it++) {
        int idx = tid + it * 256;
        int n = idx % 64, k = idx / 64;
        int ng = n0g + n;
        const float* W = (ng < GG) ? Wf : Wb;
        int nn = (ng < GG) ? ng : ng - GG;
        ws[k * 64 + n] = (k < KREAL) ? W[nn * KREAL + k] : 0.f;
    }
    __syncthreads();

    const int ty = tid / 16, tx = tid % 16;
    const int m0 = ty * 8, n0 = tx * 4;

    unsigned long long acc[4][4];   // [n][m-pair]
#pragma unroll
    for (int j = 0; j < 4; j++)
#pragma unroll
        for (int p = 0; p < 4; p++) acc[j][p] = 0ull;

#pragma unroll 4
    for (int k = 0; k < KK; k++) {
        ulonglong2 xa = *(const ulonglong2*)&xT[k * 128 + m0];
        ulonglong2 xb = *(const ulonglong2*)&xT[k * 128 + m0 + 4];
        float4 wv = *(const float4*)&ws[k * 64 + n0];
        unsigned long long w0 = dup2(wv.x), w1 = dup2(wv.y),
                           w2 = dup2(wv.z), w3 = dup2(wv.w);
        fma2(acc[0][0], w0, xa.x); fma2(acc[0][1], w0, xa.y);
        fma2(acc[0][2], w0, xb.x); fma2(acc[0][3], w0, xb.y);
        fma2(acc[1][0], w1, xa.x); fma2(acc[1][1], w1, xa.y);
        fma2(acc[1][2], w1, xb.x); fma2(acc[1][3], w1, xb.y);
        fma2(acc[2][0], w2, xa.x); fma2(acc[2][1], w2, xa.y);
        fma2(acc[2][2], w2, xb.x); fma2(acc[2][3], w2, xb.y);
        fma2(acc[3][0], w3, xa.x); fma2(acc[3][1], w3, xa.y);
        fma2(acc[3][2], w3, xb.x); fma2(acc[3][3], w3, xb.y);
    }

    // ---- epilogue: +bias, coalesced float4 stores ----
    float bias[4];
#pragma unroll
    for (int j = 0; j < 4; j++) {
        int ng = n0g + n0 + j;
        bias[j] = (ng < GG) ? bf[ng] : bb[ng - GG];
    }
    float2 u[4][4];
#pragma unroll
    for (int j = 0; j < 4; j++)
#pragma unroll
        for (int p = 0; p < 4; p++) u[j][p] = unpk(acc[j][p]);

#pragma unroll
    for (int i = 0; i < 8; i++) {
        int p = i >> 1, h = i & 1;
        float4 o;
        o.x = (h ? u[0][p].y : u[0][p].x) + bias[0];
        o.y = (h ? u[1][p].y : u[1][p].x) + bias[1];
        o.z = (h ? u[2][p].y : u[2][p].x) + bias[2];
        o.w = (h ? u[3][p].y : u[3][p].x) + bias[3];
        size_t m = (size_t)(m0g + m0 + i);
        *(float4*)&gx[m * NN2 + n0g + n0] = o;
    }
}

// ---------------------------------------------------------------------------
// Recurrence (hidden-only): h' = GRU(h, gx[t]).  384 threads / CTA, RR=4 rows.
// Thread (j = tid%192 gate, seg = tid/192 k-half).  h kept k-major [64][4]
// so f32x2 row-pairs load as ulonglong2. Partial dots reduced via smem.
// ---------------------------------------------------------------------------
__global__ void __launch_bounds__(384, 1) rec_kernel(
    const float* __restrict__ gx,   // [B*T][384], this dir at +dir*192
    const float* __restrict__ Whh_f, const float* __restrict__ bhh_f,
    const float* __restrict__ Whh_b, const float* __restrict__ bhh_b,
    float* __restrict__ out_seq,    // g_out0 or nullptr
    float* __restrict__ hT)         // g_hT or nullptr
{
    const int dir = blockIdx.y;
    const int b0  = blockIdx.x * RR;
    const int tid = threadIdx.x;
    const int j   = tid % GG;
    const int seg = tid / GG;

    const float* Whh = dir ? Whh_b : Whh_f;
    const float* bhh = dir ? bhh_b : bhh_f;

    unsigned long long whp[32];
#pragma unroll
    for (int c = 0; c < 32; c++)
        whp[c] = dup2(Whh[j * HH + seg * 32 + c]);

    __shared__ __align__(16) float h_sm[HH * RR];   // [k][r]
    __shared__ float x_sm[2][RR][GG];
    __shared__ float P_sm[2][RR][GG];
    __shared__ float bh_sm[GG];

    if (tid < GG) bh_sm[tid] = bhh[tid];
    for (int e = tid; e < HH * RR; e += 384) h_sm[e] = 0.f;

    const int er = (tid * 2) / GG, eg = (tid * 2) % GG;
    {
        int t0 = dir ? (TT - 1) : 0;
        float2 v = *(const float2*)&gx[((size_t)(b0 + er) * TT + t0) * NN2 + dir * GG + eg];
        *(float2*)&x_sm[0][er][eg] = v;
    }
    __syncthreads();

    const int tstep = dir ? -1 : 1;
    int t = dir ? (TT - 1) : 0;

    for (int s = 0; s < TT; s++, t += tstep) {
        const int cur = s & 1;
        float2 pf;
        const bool dopf = (s + 1 < TT);
        if (dopf)
            pf = *(const float2*)&gx[((size_t)(b0 + er) * TT + (t + tstep)) * NN2 + dir * GG + eg];

        unsigned long long a01 = 0ull, a23 = 0ull;
#pragma unroll
        for (int c = 0; c < 32; c++) {
            ulonglong2 h4 = *(const ulonglong2*)&h_sm[(seg * 32 + c) * 4];
            fma2(a01, whp[c], h4.x);
            fma2(a23, whp[c], h4.y);
        }
        float2 v01 = unpk(a01), v23 = unpk(a23);
        P_sm[seg][0][j] = v01.x;
        P_sm[seg][1][j] = v01.y;
        P_sm[seg][2][j] = v23.x;
        P_sm[seg][3][j] = v23.y;
        __syncthreads();

        if (tid < RR * HH) {
            const int r = tid >> 6, k = tid & 63;
            float hr = P_sm[0][r][k]       + P_sm[1][r][k]       + bh_sm[k];
            float hz = P_sm[0][r][64 + k]  + P_sm[1][r][64 + k]  + bh_sm[64 + k];
            float hn = P_sm[0][r][128 + k] + P_sm[1][r][128 + k] + bh_sm[128 + k];
            float xr = x_sm[cur][r][k];
            float xz = x_sm[cur][r][64 + k];
            float xn = x_sm[cur][r][128 + k];
            float rg = sigf(xr + hr);
            float zg = sigf(xz + hz);
            float ng = tanh_f(xn + rg * hn);
            float hv = h_sm[k * 4 + r];
            float hnew = (1.f - zg) * ng + zg * hv;
            h_sm[k * 4 + r] = hnew;
            if (out_seq)
                out_seq[((size_t)(b0 + r) * TT + t) * 128 + dir * HH + k] = hnew;
        }
        if (dopf) *(float2*)&x_sm[cur ^ 1][er][eg] = pf;
        __syncthreads();
    }

    if (hT && tid < RR * HH) {
        const int r = tid >> 6, k = tid & 63;
        hT[(b0 + r) * 128 + dir * HH + k] = h_sm[k * 4 + r];
    }
}

// ---------------------------------------------------------------------------
// Head: LayerNorm(128) -> Linear(128->64)+ReLU -> Linear(64->11)
// ---------------------------------------------------------------------------
__global__ void __launch_bounds__(128, 4) head_kernel(
    const float* __restrict__ ln_g, const float* __restrict__ ln_b,
    const float* __restrict__ W1, const float* __restrict__ b1,
    const float* __restrict__ W2, const float* __restrict__ b2,
    float* __restrict__ out)
{
    const int b = blockIdx.x;
    const int tid = threadIdx.x;
    const int lane = tid & 31, wid = tid >> 5;

    __shared__ float y_sm[128];
    __shared__ float h_sm[HH];
    __shared__ float r1[4], r2[4];
    __shared__ float stats[2];

    float e = g_hT[b * 128 + tid];
    float s1 = e, s2 = e * e;
#pragma unroll
    for (int o = 16; o; o >>= 1) {
        s1 += __shfl_down_sync(0xffffffffu, s1, o);
        s2 += __shfl_down_sync(0xffffffffu, s2, o);
    }
    if (lane == 0) { r1[wid] = s1; r2[wid] = s2; }
    __syncthreads();
    if (tid == 0) {
        float a = r1[0] + r1[1] + r1[2] + r1[3];
        float c = r2[0] + r2[1] + r2[2] + r2[3];
        float mu = a * (1.f / 128.f);
        float var = c * (1.f / 128.f) - mu * mu;
        stats[0] = mu;
        stats[1] = rsqrtf(var + 1e-5f);
    }
    __syncthreads();
    y_sm[tid] = (e - stats[0]) * stats[1] * ln_g[tid] + ln_b[tid];
    __syncthreads();

    if (tid < HH) {
        float acc = b1[tid];
#pragma unroll
        for (int k = 0; k < 128; k++) acc += W1[tid * 128 + k] * y_sm[k];
        h_sm[tid] = fmaxf(acc, 0.f);
    }
    __syncthreads();
    if (tid < OUTD) {
        float acc = b2[tid];
#pragma unroll
        for (int k = 0; k < HH; k++) acc += W2[tid * HH + k] * h_sm[k];
        out[b * OUTD + tid] = acc;
    }
}

// ---------------------------------------------------------------------------
extern "C" void kernel_launch(void* const* d_in, const int* in_sizes, int n_in,
                              void* d_out, int out_size) {
    (void)in_sizes; (void)n_in; (void)out_size;
    const float* x     = (const float*)d_in[0];
    const float* Wih00 = (const float*)d_in[1];
    const float* Whh00 = (const float*)d_in[2];
    const float* bih00 = (const float*)d_in[3];
    const float* bhh00 = (const float*)d_in[4];
    const float* Wih01 = (const float*)d_in[5];
    const float* Whh01 = (const float*)d_in[6];
    const float* bih01 = (const float*)d_in[7];
    const float* bhh01 = (const float*)d_in[8];
    const float* Wih10 = (const float*)d_in[9];
    const float* Whh10 = (const float*)d_in[10];
    const float* bih10 = (const float*)d_in[11];
    const float* bhh10 = (const float*)d_in[12];
    const float* Wih11 = (const float*)d_in[13];
    const float* Whh11 = (const float*)d_in[14];
    const float* bih11 = (const float*)d_in[15];
    const float* bhh11 = (const float*)d_in[16];
    const float* ln_g  = (const float*)d_in[17];
    const float* ln_b  = (const float*)d_in[18];
    const float* W1    = (const float*)d_in[19];
    const float* b1    = (const float*)d_in[20];
    const float* W2    = (const float*)d_in[21];
    const float* b2    = (const float*)d_in[22];
    float* out = (float*)d_out;

    float* gx0  = nullptr; cudaGetSymbolAddress((void**)&gx0,  g_gx0);
    float* gx1  = nullptr; cudaGetSymbolAddress((void**)&gx1,  g_gx1);
    float* out0 = nullptr; cudaGetSymbolAddress((void**)&out0, g_out0);
    float* hT   = nullptr; cudaGetSymbolAddress((void**)&hT,   g_hT);

    const int smem32  = (32 * 128 + 32 * 64) * 4;
    const int smem128 = (128 * 128 + 128 * 64) * 4;
    cudaFuncSetAttribute(gemm_gx_kernel<32, 29>,
                         cudaFuncAttributeMaxDynamicSharedMemorySize, smem32);
    cudaFuncSetAttribute(gemm_gx_kernel<128, 128>,
                         cudaFuncAttributeMaxDynamicSharedMemorySize, smem128);

    dim3 ggrid(MT / 128, 6);
    dim3 rgrid(BB / RR, 2);

    // layer 0 input gates (both dirs) — fully parallel
    gemm_gx_kernel<32, 29><<<ggrid, 256, smem32>>>(
        x, INP, Wih00, Wih01, bih00, bih01, gx0);
    // layer 0 scan (hidden-only), writes out0
    rec_kernel<<<rgrid, 384>>>(gx0, Whh00, bhh00, Whh01, bhh01, out0, nullptr);
    // layer 1 input gates — fully parallel
    gemm_gx_kernel<128, 128><<<ggrid, 256, smem128>>>(
        out0, 128, Wih10, Wih11, bih10, bih11, gx1);
    // layer 1 scan (hidden-only), keeps only final states
    rec_kernel<<<rgrid, 384>>>(gx1, Whh10, bhh10, Whh11, bhh11, nullptr, hT);
    // LN + MLP head
    head_kernel<<<BB, 128>>>(ln_g, ln_b, W1, b1, W2, b2, out);
}

// round 3
// speedup vs baseline: 1.4402x; 1.1228x over previous
#include <cuda_runtime.h>

#define BB   256
#define TT   2048
#define INP  29
#define HH   64
#define GG   192   // 3*H
#define NN2  384   // both directions
#define OUTD 11
#define RR   4     // batch rows per recurrence CTA
#define MT   ((size_t)BB * TT)

// Scratch (device globals — no allocation allowed)
__device__ float g_out0[(size_t)BB * TT * 2 * HH];   // [B*T][128] layer-0 bi output
__device__ float g_gx0[(size_t)BB * TT * NN2];       // [B*T][384] layer-0 input gates
__device__ float g_gx1[(size_t)BB * TT * NN2];       // [B*T][384] layer-1 input gates
__device__ float g_hT[BB * 2 * HH];                  // [B][128] final states of layer 1

// ---------------------------------------------------------------------------
// f32x2 packed helpers (Blackwell FFMA2 — 2x fp32 FMA throughput)
// ---------------------------------------------------------------------------
__device__ __forceinline__ void fma2(unsigned long long& acc,
                                     unsigned long long a, unsigned long long b) {
    asm("fma.rn.f32x2 %0, %1, %2, %0;" : "+l"(acc) : "l"(a), "l"(b));
}
__device__ __forceinline__ unsigned long long dup2(float f) {
    unsigned long long d;
    unsigned int u = __float_as_uint(f);
    asm("mov.b64 %0, {%1, %1};" : "=l"(d) : "r"(u));
    return d;
}
__device__ __forceinline__ float2 unpk(unsigned long long v) {
    unsigned int a, b;
    asm("mov.b64 {%0, %1}, %2;" : "=r"(a), "=r"(b) : "l"(v));
    float2 r; r.x = __uint_as_float(a); r.y = __uint_as_float(b);
    return r;
}

// Clamp-free fast activations (safe at +/-inf by construction).
__device__ __forceinline__ float sigf(float v) {
    float e = __expf(-v);                 // v->-inf: e=inf -> result 0; v->+inf: e=0 -> 1
    return __fdividef(1.f, 1.f + e);
}
__device__ __forceinline__ float tanh_f(float v) {
    float e = __expf(-2.f * v);           // v->-inf: e=inf -> 2/inf-1 = -1; v->+inf: 1
    return __fdividef(2.f, 1.f + e) - 1.f;
}

// ---------------------------------------------------------------------------
// Input-gate GEMM: gx[m][384] = A[m][KREAL] @ Wcat[384][KREAL]^T + bcat
// CTA tile: 128 M x 64 N, 256 threads, thread tile 8M x 4N via f32x2 M-pairs.
// ---------------------------------------------------------------------------
template<int KK, int KREAL>
__global__ void __launch_bounds__(256, 2) gemm_gx_kernel(
    const float* __restrict__ A, int lda,
    const float* __restrict__ Wf, const float* __restrict__ Wb,
    const float* __restrict__ bf, const float* __restrict__ bb,
    float* __restrict__ gx)
{
    extern __shared__ float sm[];
    float* xT = sm;               // [KK][128]
    float* ws = sm + KK * 128;    // [KK][64]

    const int tid = threadIdx.x;
    const int m0g = blockIdx.x * 128;
    const int n0g = blockIdx.y * 64;

    if (KK == KREAL) {
#pragma unroll
        for (int it = 0; it < 128 * (KK / 4) / 256; it++) {
            int idx = tid + it * 256;
            int m = idx % 128, k4 = idx / 128;
            float4 v = *(const float4*)&A[(size_t)(m0g + m) * lda + k4 * 4];
            xT[(k4 * 4 + 0) * 128 + m] = v.x;
            xT[(k4 * 4 + 1) * 128 + m] = v.y;
            xT[(k4 * 4 + 2) * 128 + m] = v.z;
            xT[(k4 * 4 + 3) * 128 + m] = v.w;
        }
    } else {
#pragma unroll
        for (int it = 0; it < 128 * KK / 256; it++) {
            int idx = tid + it * 256;
            int m = idx % 128, k = idx / 128;
            xT[k * 128 + m] = (k < KREAL) ? A[(size_t)(m0g + m) * lda + k] : 0.f;
        }
    }
#pragma unroll
    for (int it = 0; it < KK * 64 / 256; it++) {
        int idx = tid + it * 256;
        int n = idx % 64, k = idx / 64;
        int ng = n0g + n;
        const float* W = (ng < GG) ? Wf : Wb;
        int nn = (ng < GG) ? ng : ng - GG;
        ws[k * 64 + n] = (k < KREAL) ? W[nn * KREAL + k] : 0.f;
    }
    __syncthreads();

    const int ty = tid / 16, tx = tid % 16;
    const int m0 = ty * 8, n0 = tx * 4;

    unsigned long long acc[4][4];
#pragma unroll
    for (int j = 0; j < 4; j++)
#pragma unroll
        for (int p = 0; p < 4; p++) acc[j][p] = 0ull;

#pragma unroll 4
    for (int k = 0; k < KK; k++) {
        ulonglong2 xa = *(const ulonglong2*)&xT[k * 128 + m0];
        ulonglong2 xb = *(const ulonglong2*)&xT[k * 128 + m0 + 4];
        float4 wv = *(const float4*)&ws[k * 64 + n0];
        unsigned long long w0 = dup2(wv.x), w1 = dup2(wv.y),
                           w2 = dup2(wv.z), w3 = dup2(wv.w);
        fma2(acc[0][0], w0, xa.x); fma2(acc[0][1], w0, xa.y);
        fma2(acc[0][2], w0, xb.x); fma2(acc[0][3], w0, xb.y);
        fma2(acc[1][0], w1, xa.x); fma2(acc[1][1], w1, xa.y);
        fma2(acc[1][2], w1, xb.x); fma2(acc[1][3], w1, xb.y);
        fma2(acc[2][0], w2, xa.x); fma2(acc[2][1], w2, xa.y);
        fma2(acc[2][2], w2, xb.x); fma2(acc[2][3], w2, xb.y);
        fma2(acc[3][0], w3, xa.x); fma2(acc[3][1], w3, xa.y);
        fma2(acc[3][2], w3, xb.x); fma2(acc[3][3], w3, xb.y);
    }

    float bias[4];
#pragma unroll
    for (int j = 0; j < 4; j++) {
        int ng = n0g + n0 + j;
        bias[j] = (ng < GG) ? bf[ng] : bb[ng - GG];
    }
    float2 u[4][4];
#pragma unroll
    for (int j = 0; j < 4; j++)
#pragma unroll
        for (int p = 0; p < 4; p++) u[j][p] = unpk(acc[j][p]);

#pragma unroll
    for (int i = 0; i < 8; i++) {
        int p = i >> 1, h = i & 1;
        float4 o;
        o.x = (h ? u[0][p].y : u[0][p].x) + bias[0];
        o.y = (h ? u[1][p].y : u[1][p].x) + bias[1];
        o.z = (h ? u[2][p].y : u[2][p].x) + bias[2];
        o.w = (h ? u[3][p].y : u[3][p].x) + bias[3];
        size_t m = (size_t)(m0g + m0 + i);
        *(float4*)&gx[m * NN2 + n0g + n0] = o;
    }
}

// ---------------------------------------------------------------------------
// Recurrence (hidden-only), v3:
//   768 threads = 24 warps. j = tid%192 (gate), seg = tid/192 (K quarter).
//   Per-thread FFMA2 chain is 16 deep (64 cyc). gx prefetched 2 steps ahead
//   so the DRAM load has a full step of slack before its STS.
// ---------------------------------------------------------------------------
#define RBD 768
__global__ void __launch_bounds__(RBD, 1) rec_kernel(
    const float* __restrict__ gx,   // [B*T][384], this dir at +dir*192
    const float* __restrict__ Whh_f, const float* __restrict__ bhh_f,
    const float* __restrict__ Whh_b, const float* __restrict__ bhh_b,
    float* __restrict__ out_seq,    // g_out0 or nullptr
    float* __restrict__ hT)         // g_hT or nullptr
{
    const int dir = blockIdx.y;
    const int b0  = blockIdx.x * RR;
    const int tid = threadIdx.x;
    const int j   = tid % GG;
    const int seg = tid / GG;       // 0..3

    const float* Whh = dir ? Whh_b : Whh_f;
    const float* bhh = dir ? bhh_b : bhh_f;

    unsigned long long whp[16];
#pragma unroll
    for (int c = 0; c < 16; c++)
        whp[c] = dup2(Whh[j * HH + seg * 16 + c]);

    __shared__ __align__(16) float h_sm[HH * RR];     // [k][r]
    __shared__ float x_sm[2][RR][GG];
    __shared__ float P_sm[4][RR][GG];

    for (int e = tid; e < HH * RR; e += RBD) h_sm[e] = 0.f;

    // gate-math thread state (tid < 256): element (r,k), h and biases in regs
    const int gr = tid >> 6, gk = tid & 63;
    float h_reg = 0.f, bhr = 0.f, bhz = 0.f, bhn = 0.f;
    if (tid < RR * HH) {
        bhr = bhh[gk];
        bhz = bhh[64 + gk];
        bhn = bhh[128 + gk];
    }

    const int tstep = dir ? -1 : 1;
    int t = dir ? (TT - 1) : 0;

    // prefetch lane: thread -> (row=seg, gate=j), one float per thread per step
    const size_t pbase = ((size_t)(b0 + seg) * TT) * NN2 + (size_t)dir * GG + j;

    // step 0 gx -> x_sm[0] (blocking, once)
    x_sm[0][seg][j] = gx[pbase + (size_t)t * NN2];
    // prefetch for step 1
    float pf_next = (TT > 1) ? gx[pbase + (size_t)(t + tstep) * NN2] : 0.f;
    __syncthreads();

    for (int s = 0; s < TT; s++, t += tstep) {
        const int cur = s & 1;

        // issue LDG for step s+2 immediately (consumed at step s+1's store)
        float pf_next2 = 0.f;
        if (s + 2 < TT)
            pf_next2 = gx[pbase + (size_t)(t + 2 * tstep) * NN2];

        // hidden GEMV: quarter-K per thread, 4 rows via two f32x2 accumulators
        unsigned long long a01 = 0ull, a23 = 0ull;
#pragma unroll
        for (int c = 0; c < 16; c++) {
            ulonglong2 h4 = *(const ulonglong2*)&h_sm[(seg * 16 + c) * 4];
            fma2(a01, whp[c], h4.x);
            fma2(a23, whp[c], h4.y);
        }
        float2 v01 = unpk(a01), v23 = unpk(a23);
        P_sm[seg][0][j] = v01.x;
        P_sm[seg][1][j] = v01.y;
        P_sm[seg][2][j] = v23.x;
        P_sm[seg][3][j] = v23.y;

        // store gx for step s+1 (LDG was issued one full step ago)
        if (s + 1 < TT) x_sm[cur ^ 1][seg][j] = pf_next;
        pf_next = pf_next2;
        __syncthreads();

        if (tid < RR * HH) {
            float hr = P_sm[0][gr][gk]       + P_sm[1][gr][gk]
                     + P_sm[2][gr][gk]       + P_sm[3][gr][gk]       + bhr;
            float hz = P_sm[0][gr][64 + gk]  + P_sm[1][gr][64 + gk]
                     + P_sm[2][gr][64 + gk]  + P_sm[3][gr][64 + gk]  + bhz;
            float hn = P_sm[0][gr][128 + gk] + P_sm[1][gr][128 + gk]
                     + P_sm[2][gr][128 + gk] + P_sm[3][gr][128 + gk] + bhn;
            float rg = sigf(x_sm[cur][gr][gk]       + hr);
            float zg = sigf(x_sm[cur][gr][64 + gk]  + hz);
            float ng = tanh_f(x_sm[cur][gr][128 + gk] + rg * hn);
            h_reg = (1.f - zg) * ng + zg * h_reg;
            h_sm[gk * 4 + gr] = h_reg;
            if (out_seq)
                out_seq[((size_t)(b0 + gr) * TT + t) * 128 + dir * HH + gk] = h_reg;
        }
        __syncthreads();
    }

    if (hT && tid < RR * HH)
        hT[(b0 + gr) * 128 + dir * HH + gk] = h_reg;
}

// ---------------------------------------------------------------------------
// Head: LayerNorm(128) -> Linear(128->64)+ReLU -> Linear(64->11)
// ---------------------------------------------------------------------------
__global__ void __launch_bounds__(128, 4) head_kernel(
    const float* __restrict__ ln_g, const float* __restrict__ ln_b,
    const float* __restrict__ W1, const float* __restrict__ b1,
    const float* __restrict__ W2, const float* __restrict__ b2,
    float* __restrict__ out)
{
    const int b = blockIdx.x;
    const int tid = threadIdx.x;
    const int lane = tid & 31, wid = tid >> 5;

    __shared__ float y_sm[128];
    __shared__ float h_sm[HH];
    __shared__ float r1[4], r2[4];
    __shared__ float stats[2];

    float e = g_hT[b * 128 + tid];
    float s1 = e, s2 = e * e;
#pragma unroll
    for (int o = 16; o; o >>= 1) {
        s1 += __shfl_down_sync(0xffffffffu, s1, o);
        s2 += __shfl_down_sync(0xffffffffu, s2, o);
    }
    if (lane == 0) { r1[wid] = s1; r2[wid] = s2; }
    __syncthreads();
    if (tid == 0) {
        float a = r1[0] + r1[1] + r1[2] + r1[3];
        float c = r2[0] + r2[1] + r2[2] + r2[3];
        float mu = a * (1.f / 128.f);
        float var = c * (1.f / 128.f) - mu * mu;
        stats[0] = mu;
        stats[1] = rsqrtf(var + 1e-5f);
    }
    __syncthreads();
    y_sm[tid] = (e - stats[0]) * stats[1] * ln_g[tid] + ln_b[tid];
    __syncthreads();

    if (tid < HH) {
        float acc = b1[tid];
#pragma unroll
        for (int k = 0; k < 128; k++) acc += W1[tid * 128 + k] * y_sm[k];
        h_sm[tid] = fmaxf(acc, 0.f);
    }
    __syncthreads();
    if (tid < OUTD) {
        float acc = b2[tid];
#pragma unroll
        for (int k = 0; k < HH; k++) acc += W2[tid * HH + k] * h_sm[k];
        out[b * OUTD + tid] = acc;
    }
}

// ---------------------------------------------------------------------------
extern "C" void kernel_launch(void* const* d_in, const int* in_sizes, int n_in,
                              void* d_out, int out_size) {
    (void)in_sizes; (void)n_in; (void)out_size;
    const float* x     = (const float*)d_in[0];
    const float* Wih00 = (const float*)d_in[1];
    const float* Whh00 = (const float*)d_in[2];
    const float* bih00 = (const float*)d_in[3];
    const float* bhh00 = (const float*)d_in[4];
    const float* Wih01 = (const float*)d_in[5];
    const float* Whh01 = (const float*)d_in[6];
    const float* bih01 = (const float*)d_in[7];
    const float* bhh01 = (const float*)d_in[8];
    const float* Wih10 = (const float*)d_in[9];
    const float* Whh10 = (const float*)d_in[10];
    const float* bih10 = (const float*)d_in[11];
    const float* bhh10 = (const float*)d_in[12];
    const float* Wih11 = (const float*)d_in[13];
    const float* Whh11 = (const float*)d_in[14];
    const float* bih11 = (const float*)d_in[15];
    const float* bhh11 = (const float*)d_in[16];
    const float* ln_g  = (const float*)d_in[17];
    const float* ln_b  = (const float*)d_in[18];
    const float* W1    = (const float*)d_in[19];
    const float* b1    = (const float*)d_in[20];
    const float* W2    = (const float*)d_in[21];
    const float* b2    = (const float*)d_in[22];
    float* out = (float*)d_out;

    float* gx0  = nullptr; cudaGetSymbolAddress((void**)&gx0,  g_gx0);
    float* gx1  = nullptr; cudaGetSymbolAddress((void**)&gx1,  g_gx1);
    float* out0 = nullptr; cudaGetSymbolAddress((void**)&out0, g_out0);
    float* hT   = nullptr; cudaGetSymbolAddress((void**)&hT,   g_hT);

    const int smem32  = (32 * 128 + 32 * 64) * 4;
    const int smem128 = (128 * 128 + 128 * 64) * 4;
    cudaFuncSetAttribute(gemm_gx_kernel<32, 29>,
                         cudaFuncAttributeMaxDynamicSharedMemorySize, smem32);
    cudaFuncSetAttribute(gemm_gx_kernel<128, 128>,
                         cudaFuncAttributeMaxDynamicSharedMemorySize, smem128);

    dim3 ggrid(MT / 128, 6);
    dim3 rgrid(BB / RR, 2);

    gemm_gx_kernel<32, 29><<<ggrid, 256, smem32>>>(
        x, INP, Wih00, Wih01, bih00, bih01, gx0);
    rec_kernel<<<rgrid, RBD>>>(gx0, Whh00, bhh00, Whh01, bhh01, out0, nullptr);
    gemm_gx_kernel<128, 128><<<ggrid, 256, smem128>>>(
        out0, 128, Wih10, Wih11, bih10, bih11, gx1);
    rec_kernel<<<rgrid, RBD>>>(gx1, Whh10, bhh10, Whh11, bhh11, nullptr, hT);
    head_kernel<<<BB, 128>>>(ln_g, ln_b, W1, b1, W2, b2, out);
}

// round 4
// speedup vs baseline: 1.5267x; 1.0600x over previous
#include <cuda_runtime.h>

#define BB   256
#define TT   2048
#define INP  29
#define HH   64
#define GG   192   // 3*H
#define NN2  384   // both directions
#define OUTD 11
#define RR   4     // batch rows per recurrence CTA
#define MT   ((size_t)BB * TT)

// Scratch (device globals — no allocation allowed)
__device__ float g_out0[(size_t)BB * TT * 2 * HH];   // [B*T][128] layer-0 bi output
__device__ float g_gx0[(size_t)BB * TT * NN2];       // [B*T][384] layer-0 input gates
__device__ float g_gx1[(size_t)BB * TT * NN2];       // [B*T][384] layer-1 input gates
__device__ float g_hT[BB * 2 * HH];                  // [B][128] final states of layer 1

// ---------------------------------------------------------------------------
// f32x2 packed helpers (Blackwell FFMA2 — 2x fp32 FMA throughput)
// ---------------------------------------------------------------------------
__device__ __forceinline__ void fma2(unsigned long long& acc,
                                     unsigned long long a, unsigned long long b) {
    asm("fma.rn.f32x2 %0, %1, %2, %0;" : "+l"(acc) : "l"(a), "l"(b));
}
__device__ __forceinline__ unsigned long long dup2(float f) {
    unsigned long long d;
    unsigned int u = __float_as_uint(f);
    asm("mov.b64 %0, {%1, %1};" : "=l"(d) : "r"(u));
    return d;
}
__device__ __forceinline__ float2 unpk(unsigned long long v) {
    unsigned int a, b;
    asm("mov.b64 {%0, %1}, %2;" : "=r"(a), "=r"(b) : "l"(v));
    float2 r; r.x = __uint_as_float(a); r.y = __uint_as_float(b);
    return r;
}

// Clamp-free fast activations (safe at +/-inf by construction).
__device__ __forceinline__ float sigf(float v) {
    float e = __expf(-v);
    return __fdividef(1.f, 1.f + e);
}
__device__ __forceinline__ float tanh_f(float v) {
    float e = __expf(-2.f * v);
    return __fdividef(2.f, 1.f + e) - 1.f;
}

// ---------------------------------------------------------------------------
// Input-gate GEMM: gx[m][384] = A[m][KREAL] @ Wcat[384][KREAL]^T + bcat
// CTA tile: 128 M x 64 N, 256 threads, thread tile 8M x 4N via f32x2 M-pairs.
// ---------------------------------------------------------------------------
template<int KK, int KREAL>
__global__ void __launch_bounds__(256, 2) gemm_gx_kernel(
    const float* __restrict__ A, int lda,
    const float* __restrict__ Wf, const float* __restrict__ Wb,
    const float* __restrict__ bf, const float* __restrict__ bb,
    float* __restrict__ gx)
{
    extern __shared__ float sm[];
    float* xT = sm;               // [KK][128]
    float* ws = sm + KK * 128;    // [KK][64]

    const int tid = threadIdx.x;
    const int m0g = blockIdx.x * 128;
    const int n0g = blockIdx.y * 64;

    if (KK == KREAL) {
#pragma unroll
        for (int it = 0; it < 128 * (KK / 4) / 256; it++) {
            int idx = tid + it * 256;
            int m = idx % 128, k4 = idx / 128;
            float4 v = *(const float4*)&A[(size_t)(m0g + m) * lda + k4 * 4];
            xT[(k4 * 4 + 0) * 128 + m] = v.x;
            xT[(k4 * 4 + 1) * 128 + m] = v.y;
            xT[(k4 * 4 + 2) * 128 + m] = v.z;
            xT[(k4 * 4 + 3) * 128 + m] = v.w;
        }
    } else {
#pragma unroll
        for (int it = 0; it < 128 * KK / 256; it++) {
            int idx = tid + it * 256;
            int m = idx % 128, k = idx / 128;
            xT[k * 128 + m] = (k < KREAL) ? A[(size_t)(m0g + m) * lda + k] : 0.f;
        }
    }
#pragma unroll
    for (int it = 0; it < KK * 64 / 256; it++) {
        int idx = tid + it * 256;
        int n = idx % 64, k = idx / 64;
        int ng = n0g + n;
        const float* W = (ng < GG) ? Wf : Wb;
        int nn = (ng < GG) ? ng : ng - GG;
        ws[k * 64 + n] = (k < KREAL) ? W[nn * KREAL + k] : 0.f;
    }
    __syncthreads();

    const int ty = tid / 16, tx = tid % 16;
    const int m0 = ty * 8, n0 = tx * 4;

    unsigned long long acc[4][4];
#pragma unroll
    for (int j = 0; j < 4; j++)
#pragma unroll
        for (int p = 0; p < 4; p++) acc[j][p] = 0ull;

#pragma unroll 4
    for (int k = 0; k < KK; k++) {
        ulonglong2 xa = *(const ulonglong2*)&xT[k * 128 + m0];
        ulonglong2 xb = *(const ulonglong2*)&xT[k * 128 + m0 + 4];
        float4 wv = *(const float4*)&ws[k * 64 + n0];
        unsigned long long w0 = dup2(wv.x), w1 = dup2(wv.y),
                           w2 = dup2(wv.z), w3 = dup2(wv.w);
        fma2(acc[0][0], w0, xa.x); fma2(acc[0][1], w0, xa.y);
        fma2(acc[0][2], w0, xb.x); fma2(acc[0][3], w0, xb.y);
        fma2(acc[1][0], w1, xa.x); fma2(acc[1][1], w1, xa.y);
        fma2(acc[1][2], w1, xb.x); fma2(acc[1][3], w1, xb.y);
        fma2(acc[2][0], w2, xa.x); fma2(acc[2][1], w2, xa.y);
        fma2(acc[2][2], w2, xb.x); fma2(acc[2][3], w2, xb.y);
        fma2(acc[3][0], w3, xa.x); fma2(acc[3][1], w3, xa.y);
        fma2(acc[3][2], w3, xb.x); fma2(acc[3][3], w3, xb.y);
    }

    float bias[4];
#pragma unroll
    for (int j = 0; j < 4; j++) {
        int ng = n0g + n0 + j;
        bias[j] = (ng < GG) ? bf[ng] : bb[ng - GG];
    }
    float2 u[4][4];
#pragma unroll
    for (int j = 0; j < 4; j++)
#pragma unroll
        for (int p = 0; p < 4; p++) u[j][p] = unpk(acc[j][p]);

#pragma unroll
    for (int i = 0; i < 8; i++) {
        int p = i >> 1, h = i & 1;
        float4 o;
        o.x = (h ? u[0][p].y : u[0][p].x) + bias[0];
        o.y = (h ? u[1][p].y : u[1][p].x) + bias[1];
        o.z = (h ? u[2][p].y : u[2][p].x) + bias[2];
        o.w = (h ? u[3][p].y : u[3][p].x) + bias[3];
        size_t m = (size_t)(m0g + m0 + i);
        *(float4*)&gx[m * NN2 + n0g + n0] = o;
    }
}

// ---------------------------------------------------------------------------
// Recurrence (hidden-only), v4: fat-j threads to halve smem crossbar traffic.
//   384 threads = 12 warps. Thread = (j2 = tid%96, seg = tid/96).
//   Owns gate rows j = 2*j2, 2*j2+1 and K-quarter seg (16 c's).
//   One 16B h-broadcast load feeds 4 FFMA2 (2 j x 2 row-pairs).
//   gx prefetched 2 steps ahead; P partials stored as STS.64.
// ---------------------------------------------------------------------------
#define RBD 384
__global__ void __launch_bounds__(RBD, 1) rec_kernel(
    const float* __restrict__ gx,   // [B*T][384], this dir at +dir*192
    const float* __restrict__ Whh_f, const float* __restrict__ bhh_f,
    const float* __restrict__ Whh_b, const float* __restrict__ bhh_b,
    float* __restrict__ out_seq,    // g_out0 or nullptr
    float* __restrict__ hT)         // g_hT or nullptr
{
    const int dir = blockIdx.y;
    const int b0  = blockIdx.x * RR;
    const int tid = threadIdx.x;
    const int j2  = tid % 96;       // gate-row pair
    const int seg = tid / 96;       // 0..3  (uniform within each warp)

    const float* Whh = dir ? Whh_b : Whh_f;
    const float* bhh = dir ? bhh_b : bhh_f;

    // duplicated weights: [jj][c] for j = 2*j2+jj, c in seg*16..+16
    unsigned long long whp[2][16];
#pragma unroll
    for (int jj = 0; jj < 2; jj++)
#pragma unroll
        for (int c = 0; c < 16; c++)
            whp[jj][c] = dup2(Whh[(j2 * 2 + jj) * HH + seg * 16 + c]);

    __shared__ __align__(16) float h_sm[HH * RR];     // [k][r]
    __shared__ __align__(8)  float x_sm[2][RR][GG];
    __shared__ __align__(8)  float P_sm[4][RR][GG];

    for (int e = tid; e < HH * RR; e += RBD) h_sm[e] = 0.f;

    // gate-math thread state (tid < 256): element (r,k)
    const int gr = tid >> 6, gk = tid & 63;
    float h_reg = 0.f, bhr = 0.f, bhz = 0.f, bhn = 0.f;
    if (tid < RR * HH) {
        bhr = bhh[gk];
        bhz = bhh[64 + gk];
        bhn = bhh[128 + gk];
    }

    const int tstep = dir ? -1 : 1;
    int t = dir ? (TT - 1) : 0;

    // prefetch lane: 768 gx floats/step over 384 threads -> float2 each
    const int pe = tid * 2;
    const int pr = pe / GG, pg = pe % GG;
    const size_t pbase = ((size_t)(b0 + pr) * TT) * NN2 + (size_t)dir * GG + pg;

    *(float2*)&x_sm[0][pr][pg] = *(const float2*)&gx[pbase + (size_t)t * NN2];
    float2 pf_next = (TT > 1) ? *(const float2*)&gx[pbase + (size_t)(t + tstep) * NN2]
                              : make_float2(0.f, 0.f);
    __syncthreads();

    for (int s = 0; s < TT; s++, t += tstep) {
        const int cur = s & 1;

        // issue LDG for step s+2 now (consumed at step s+1's store)
        float2 pf_next2 = make_float2(0.f, 0.f);
        if (s + 2 < TT)
            pf_next2 = *(const float2*)&gx[pbase + (size_t)(t + 2 * tstep) * NN2];

        // hidden GEMV: 2 gate rows x 4 batch rows, quarter-K
        unsigned long long a0_01 = 0ull, a0_23 = 0ull;
        unsigned long long a1_01 = 0ull, a1_23 = 0ull;
#pragma unroll
        for (int c = 0; c < 16; c++) {
            ulonglong2 h4 = *(const ulonglong2*)&h_sm[(seg * 16 + c) * 4];
            fma2(a0_01, whp[0][c], h4.x);
            fma2(a0_23, whp[0][c], h4.y);
            fma2(a1_01, whp[1][c], h4.x);
            fma2(a1_23, whp[1][c], h4.y);
        }
        {
            float2 v0a = unpk(a0_01), v0b = unpk(a0_23);
            float2 v1a = unpk(a1_01), v1b = unpk(a1_23);
            const int j0 = j2 * 2;
            *(float2*)&P_sm[seg][0][j0] = make_float2(v0a.x, v1a.x);
            *(float2*)&P_sm[seg][1][j0] = make_float2(v0a.y, v1a.y);
            *(float2*)&P_sm[seg][2][j0] = make_float2(v0b.x, v1b.x);
            *(float2*)&P_sm[seg][3][j0] = make_float2(v0b.y, v1b.y);
        }

        // store gx for step s+1 (its LDG was issued one full step ago)
        if (s + 1 < TT) *(float2*)&x_sm[cur ^ 1][pr][pg] = pf_next;
        pf_next = pf_next2;
        __syncthreads();

        if (tid < RR * HH) {
            float hr = P_sm[0][gr][gk]       + P_sm[1][gr][gk]
                     + P_sm[2][gr][gk]       + P_sm[3][gr][gk]       + bhr;
            float hz = P_sm[0][gr][64 + gk]  + P_sm[1][gr][64 + gk]
                     + P_sm[2][gr][64 + gk]  + P_sm[3][gr][64 + gk]  + bhz;
            float hn = P_sm[0][gr][128 + gk] + P_sm[1][gr][128 + gk]
                     + P_sm[2][gr][128 + gk] + P_sm[3][gr][128 + gk] + bhn;
            float rg = sigf(x_sm[cur][gr][gk]       + hr);
            float zg = sigf(x_sm[cur][gr][64 + gk]  + hz);
            float ng = tanh_f(x_sm[cur][gr][128 + gk] + rg * hn);
            h_reg = (1.f - zg) * ng + zg * h_reg;
            h_sm[gk * 4 + gr] = h_reg;
            if (out_seq)
                out_seq[((size_t)(b0 + gr) * TT + t) * 128 + dir * HH + gk] = h_reg;
        }
        __syncthreads();
    }

    if (hT && tid < RR * HH)
        hT[(b0 + gr) * 128 + dir * HH + gk] = h_reg;
}

// ---------------------------------------------------------------------------
// Head: LayerNorm(128) -> Linear(128->64)+ReLU -> Linear(64->11)
// ---------------------------------------------------------------------------
__global__ void __launch_bounds__(128, 4) head_kernel(
    const float* __restrict__ ln_g, const float* __restrict__ ln_b,
    const float* __restrict__ W1, const float* __restrict__ b1,
    const float* __restrict__ W2, const float* __restrict__ b2,
    float* __restrict__ out)
{
    const int b = blockIdx.x;
    const int tid = threadIdx.x;
    const int lane = tid & 31, wid = tid >> 5;

    __shared__ float y_sm[128];
    __shared__ float h_sm[HH];
    __shared__ float r1[4], r2[4];
    __shared__ float stats[2];

    float e = g_hT[b * 128 + tid];
    float s1 = e, s2 = e * e;
#pragma unroll
    for (int o = 16; o; o >>= 1) {
        s1 += __shfl_down_sync(0xffffffffu, s1, o);
        s2 += __shfl_down_sync(0xffffffffu, s2, o);
    }
    if (lane == 0) { r1[wid] = s1; r2[wid] = s2; }
    __syncthreads();
    if (tid == 0) {
        float a = r1[0] + r1[1] + r1[2] + r1[3];
        float c = r2[0] + r2[1] + r2[2] + r2[3];
        float mu = a * (1.f / 128.f);
        float var = c * (1.f / 128.f) - mu * mu;
        stats[0] = mu;
        stats[1] = rsqrtf(var + 1e-5f);
    }
    __syncthreads();
    y_sm[tid] = (e - stats[0]) * stats[1] * ln_g[tid] + ln_b[tid];
    __syncthreads();

    if (tid < HH) {
        float acc = b1[tid];
#pragma unroll
        for (int k = 0; k < 128; k++) acc += W1[tid * 128 + k] * y_sm[k];
        h_sm[tid] = fmaxf(acc, 0.f);
    }
    __syncthreads();
    if (tid < OUTD) {
        float acc = b2[tid];
#pragma unroll
        for (int k = 0; k < HH; k++) acc += W2[tid * HH + k] * h_sm[k];
        out[b * OUTD + tid] = acc;
    }
}

// ---------------------------------------------------------------------------
extern "C" void kernel_launch(void* const* d_in, const int* in_sizes, int n_in,
                              void* d_out, int out_size) {
    (void)in_sizes; (void)n_in; (void)out_size;
    const float* x     = (const float*)d_in[0];
    const float* Wih00 = (const float*)d_in[1];
    const float* Whh00 = (const float*)d_in[2];
    const float* bih00 = (const float*)d_in[3];
    const float* bhh00 = (const float*)d_in[4];
    const float* Wih01 = (const float*)d_in[5];
    const float* Whh01 = (const float*)d_in[6];
    const float* bih01 = (const float*)d_in[7];
    const float* bhh01 = (const float*)d_in[8];
    const float* Wih10 = (const float*)d_in[9];
    const float* Whh10 = (const float*)d_in[10];
    const float* bih10 = (const float*)d_in[11];
    const float* bhh10 = (const float*)d_in[12];
    const float* Wih11 = (const float*)d_in[13];
    const float* Whh11 = (const float*)d_in[14];
    const float* bih11 = (const float*)d_in[15];
    const float* bhh11 = (const float*)d_in[16];
    const float* ln_g  = (const float*)d_in[17];
    const float* ln_b  = (const float*)d_in[18];
    const float* W1    = (const float*)d_in[19];
    const float* b1    = (const float*)d_in[20];
    const float* W2    = (const float*)d_in[21];
    const float* b2    = (const float*)d_in[22];
    float* out = (float*)d_out;

    float* gx0  = nullptr; cudaGetSymbolAddress((void**)&gx0,  g_gx0);
    float* gx1  = nullptr; cudaGetSymbolAddress((void**)&gx1,  g_gx1);
    float* out0 = nullptr; cudaGetSymbolAddress((void**)&out0, g_out0);
    float* hT   = nullptr; cudaGetSymbolAddress((void**)&hT,   g_hT);

    const int smem32  = (32 * 128 + 32 * 64) * 4;
    const int smem128 = (128 * 128 + 128 * 64) * 4;
    cudaFuncSetAttribute(gemm_gx_kernel<32, 29>,
                         cudaFuncAttributeMaxDynamicSharedMemorySize, smem32);
    cudaFuncSetAttribute(gemm_gx_kernel<128, 128>,
                         cudaFuncAttributeMaxDynamicSharedMemorySize, smem128);

    dim3 ggrid(MT / 128, 6);
    dim3 rgrid(BB / RR, 2);

    gemm_gx_kernel<32, 29><<<ggrid, 256, smem32>>>(
        x, INP, Wih00, Wih01, bih00, bih01, gx0);
    rec_kernel<<<rgrid, RBD>>>(gx0, Whh00, bhh00, Whh01, bhh01, out0, nullptr);
    gemm_gx_kernel<128, 128><<<ggrid, 256, smem128>>>(
        out0, 128, Wih10, Wih11, bih10, bih11, gx1);
    rec_kernel<<<rgrid, RBD>>>(gx1, Whh10, bhh10, Whh11, bhh11, nullptr, hT);
    head_kernel<<<BB, 128>>>(ln_g, ln_b, W1, b1, W2, b2, out);
}

// round 5
// speedup vs baseline: 1.6531x; 1.0829x over previous
#include <cuda_runtime.h>

#define BB   256
#define TT   2048
#define INP  29
#define HH   64
#define GG   192   // 3*H
#define NN2  384   // both directions
#define OUTD 11
#define RR   4     // batch rows per recurrence CTA
#define MT   ((size_t)BB * TT)

// Scratch (device globals — no allocation allowed)
__device__ float g_out0[(size_t)BB * TT * 2 * HH];   // [B*T][128] layer-0 bi output
__device__ float g_gx0[(size_t)BB * TT * NN2];       // [B*T][384] layer-0 input gates
__device__ float g_gx1[(size_t)BB * TT * NN2];       // [B*T][384] layer-1 input gates
__device__ float g_hT[BB * 2 * HH];                  // [B][128] final states of layer 1
__device__ float g_Wt0[32 * NN2];                    // transposed layer-0 Wih (padded K=32)
__device__ float g_Wt1[128 * NN2];                   // transposed layer-1 Wih

// ---------------------------------------------------------------------------
// f32x2 packed helpers (Blackwell FFMA2 — 2x fp32 FMA throughput)
// ---------------------------------------------------------------------------
__device__ __forceinline__ void fma2(unsigned long long& acc,
                                     unsigned long long a, unsigned long long b) {
    asm("fma.rn.f32x2 %0, %1, %2, %0;" : "+l"(acc) : "l"(a), "l"(b));
}
__device__ __forceinline__ unsigned long long dup2(float f) {
    unsigned long long d;
    unsigned int u = __float_as_uint(f);
    asm("mov.b64 %0, {%1, %1};" : "=l"(d) : "r"(u));
    return d;
}
__device__ __forceinline__ float2 unpk(unsigned long long v) {
    unsigned int a, b;
    asm("mov.b64 {%0, %1}, %2;" : "=r"(a), "=r"(b) : "l"(v));
    float2 r; r.x = __uint_as_float(a); r.y = __uint_as_float(b);
    return r;
}

// Clamp-free fast activations (safe at +/-inf by construction).
__device__ __forceinline__ float sigf(float v) {
    float e = __expf(-v);
    return __fdividef(1.f, 1.f + e);
}
__device__ __forceinline__ float tanh_f(float v) {
    float e = __expf(-2.f * v);
    return __fdividef(2.f, 1.f + e) - 1.f;
}

// ---------------------------------------------------------------------------
// One-time W transpose: Wt[k][384] (zero-padded in k), coalesced writes.
// ---------------------------------------------------------------------------
__global__ void transpose_w_kernel(const float* __restrict__ Wf,
                                   const float* __restrict__ Wb,
                                   float* __restrict__ Wt,
                                   int K, int KREAL)
{
    int idx = blockIdx.x * 256 + threadIdx.x;
    if (idx >= K * NN2) return;
    int n = idx % NN2, k = idx / NN2;
    const float* W = (n < GG) ? Wf : Wb;
    int nn = (n < GG) ? n : n - GG;
    Wt[(size_t)k * NN2 + n] = (k < KREAL) ? W[nn * KREAL + k] : 0.f;
}

// ---------------------------------------------------------------------------
// Input-gate GEMM: gx[m][384] = A[m][KREAL] @ Wt[KK][384] + bcat
// CTA tile: 128 M x 64 N, 256 threads, thread tile 8M x 4N via f32x2 M-pairs.
// W now loaded from pre-transposed Wt — fully coalesced float4.
// ---------------------------------------------------------------------------
template<int KK, int KREAL>
__global__ void __launch_bounds__(256, 2) gemm_gx_kernel(
    const float* __restrict__ A, int lda,
    const float* __restrict__ Wt,
    const float* __restrict__ bf, const float* __restrict__ bb,
    float* __restrict__ gx)
{
    extern __shared__ float sm[];
    float* xT = sm;               // [KK][128]
    float* ws = sm + KK * 128;    // [KK][64]

    const int tid = threadIdx.x;
    const int m0g = blockIdx.x * 128;
    const int n0g = blockIdx.y * 64;

    if (KK == KREAL) {
#pragma unroll
        for (int it = 0; it < 128 * (KK / 4) / 256; it++) {
            int idx = tid + it * 256;
            int m = idx % 128, k4 = idx / 128;
            float4 v = *(const float4*)&A[(size_t)(m0g + m) * lda + k4 * 4];
            xT[(k4 * 4 + 0) * 128 + m] = v.x;
            xT[(k4 * 4 + 1) * 128 + m] = v.y;
            xT[(k4 * 4 + 2) * 128 + m] = v.z;
            xT[(k4 * 4 + 3) * 128 + m] = v.w;
        }
    } else {
#pragma unroll
        for (int it = 0; it < 128 * KK / 256; it++) {
            int idx = tid + it * 256;
            int m = idx % 128, k = idx / 128;
            xT[k * 128 + m] = (k < KREAL) ? A[(size_t)(m0g + m) * lda + k] : 0.f;
        }
    }
    // coalesced W tile load: KK x 16 float4s
#pragma unroll
    for (int it = 0; it < KK * 16 / 256; it++) {
        int idx = tid + it * 256;
        int n4 = idx % 16, k = idx / 16;
        *(float4*)&ws[k * 64 + n4 * 4] =
            *(const float4*)&Wt[(size_t)k * NN2 + n0g + n4 * 4];
    }
    __syncthreads();

    const int ty = tid / 16, tx = tid % 16;
    const int m0 = ty * 8, n0 = tx * 4;

    unsigned long long acc[4][4];
#pragma unroll
    for (int j = 0; j < 4; j++)
#pragma unroll
        for (int p = 0; p < 4; p++) acc[j][p] = 0ull;

#pragma unroll 4
    for (int k = 0; k < KK; k++) {
        ulonglong2 xa = *(const ulonglong2*)&xT[k * 128 + m0];
        ulonglong2 xb = *(const ulonglong2*)&xT[k * 128 + m0 + 4];
        float4 wv = *(const float4*)&ws[k * 64 + n0];
        unsigned long long w0 = dup2(wv.x), w1 = dup2(wv.y),
                           w2 = dup2(wv.z), w3 = dup2(wv.w);
        fma2(acc[0][0], w0, xa.x); fma2(acc[0][1], w0, xa.y);
        fma2(acc[0][2], w0, xb.x); fma2(acc[0][3], w0, xb.y);
        fma2(acc[1][0], w1, xa.x); fma2(acc[1][1], w1, xa.y);
        fma2(acc[1][2], w1, xb.x); fma2(acc[1][3], w1, xb.y);
        fma2(acc[2][0], w2, xa.x); fma2(acc[2][1], w2, xa.y);
        fma2(acc[2][2], w2, xb.x); fma2(acc[2][3], w2, xb.y);
        fma2(acc[3][0], w3, xa.x); fma2(acc[3][1], w3, xa.y);
        fma2(acc[3][2], w3, xb.x); fma2(acc[3][3], w3, xb.y);
    }

    float bias[4];
#pragma unroll
    for (int j = 0; j < 4; j++) {
        int ng = n0g + n0 + j;
        bias[j] = (ng < GG) ? bf[ng] : bb[ng - GG];
    }
    float2 u[4][4];
#pragma unroll
    for (int j = 0; j < 4; j++)
#pragma unroll
        for (int p = 0; p < 4; p++) u[j][p] = unpk(acc[j][p]);

#pragma unroll
    for (int i = 0; i < 8; i++) {
        int p = i >> 1, h = i & 1;
        float4 o;
        o.x = (h ? u[0][p].y : u[0][p].x) + bias[0];
        o.y = (h ? u[1][p].y : u[1][p].x) + bias[1];
        o.z = (h ? u[2][p].y : u[2][p].x) + bias[2];
        o.w = (h ? u[3][p].y : u[3][p].x) + bias[3];
        size_t m = (size_t)(m0g + m0 + i);
        *(float4*)&gx[m * NN2 + n0g + n0] = o;
    }
}

// ---------------------------------------------------------------------------
// Recurrence (hidden-only), v5: 768 threads = 24 warps.
//   Thread = (j2 = tid%96 gate-row pair, seg = tid/96 K-eighth of 8 c's).
//   One 16B h-broadcast load feeds 4 FFMA2. gx prefetched 2 steps ahead by
//   192 threads doing LDG.128 (halved LSU issue vs v4).
// ---------------------------------------------------------------------------
#define RBD 768
__global__ void __launch_bounds__(RBD, 1) rec_kernel(
    const float* __restrict__ gx,   // [B*T][384], this dir at +dir*192
    const float* __restrict__ Whh_f, const float* __restrict__ bhh_f,
    const float* __restrict__ Whh_b, const float* __restrict__ bhh_b,
    float* __restrict__ out_seq,    // g_out0 or nullptr
    float* __restrict__ hT)         // g_hT or nullptr
{
    const int dir = blockIdx.y;
    const int b0  = blockIdx.x * RR;
    const int tid = threadIdx.x;
    const int j2  = tid % 96;       // gate-row pair
    const int seg = tid / 96;       // 0..7  (uniform within each warp)

    const float* Whh = dir ? Whh_b : Whh_f;
    const float* bhh = dir ? bhh_b : bhh_f;

    // duplicated weights: [jj][c] for j = 2*j2+jj, c in seg*8..+8
    unsigned long long whp[2][8];
#pragma unroll
    for (int jj = 0; jj < 2; jj++)
#pragma unroll
        for (int c = 0; c < 8; c++)
            whp[jj][c] = dup2(Whh[(j2 * 2 + jj) * HH + seg * 8 + c]);

    __shared__ __align__(16) float h_sm[HH * RR];     // [k][r]
    __shared__ __align__(16) float x_sm[2][RR][GG];
    __shared__ __align__(8)  float P_sm[8][RR][GG];

    if (tid < HH * RR) h_sm[tid] = 0.f;

    // gate-math thread state (tid < 256): element (r,k)
    const int gr = tid >> 6, gk = tid & 63;
    float h_reg = 0.f, bhr = 0.f, bhz = 0.f, bhn = 0.f;
    if (tid < RR * HH) {
        bhr = bhh[gk];
        bhz = bhh[64 + gk];
        bhn = bhh[128 + gk];
    }

    const int tstep = dir ? -1 : 1;
    int t = dir ? (TT - 1) : 0;

    // prefetch lanes: 768 gx floats/step, 192 threads x LDG.128
    const int pe = tid * 4;
    const int pr = pe / GG, pg = pe % GG;
    const size_t pbase = ((size_t)(b0 + pr) * TT) * NN2 + (size_t)dir * GG + pg;
    const bool pf_lane = (tid < 192);

    float4 pf_next = make_float4(0.f, 0.f, 0.f, 0.f);
    if (pf_lane) {
        *(float4*)&x_sm[0][pr][pg] = *(const float4*)&gx[pbase + (size_t)t * NN2];
        if (TT > 1)
            pf_next = *(const float4*)&gx[pbase + (size_t)(t + tstep) * NN2];
    }
    __syncthreads();

    for (int s = 0; s < TT; s++, t += tstep) {
        const int cur = s & 1;

        // issue LDG for step s+2 now (consumed at step s+1's store)
        float4 pf_next2 = make_float4(0.f, 0.f, 0.f, 0.f);
        if (pf_lane && s + 2 < TT)
            pf_next2 = *(const float4*)&gx[pbase + (size_t)(t + 2 * tstep) * NN2];

        // hidden GEMV: 2 gate rows x 4 batch rows, eighth-K
        unsigned long long a0_01 = 0ull, a0_23 = 0ull;
        unsigned long long a1_01 = 0ull, a1_23 = 0ull;
#pragma unroll
        for (int c = 0; c < 8; c++) {
            ulonglong2 h4 = *(const ulonglong2*)&h_sm[(seg * 8 + c) * 4];
            fma2(a0_01, whp[0][c], h4.x);
            fma2(a0_23, whp[0][c], h4.y);
            fma2(a1_01, whp[1][c], h4.x);
            fma2(a1_23, whp[1][c], h4.y);
        }
        {
            float2 v0a = unpk(a0_01), v0b = unpk(a0_23);
            float2 v1a = unpk(a1_01), v1b = unpk(a1_23);
            const int j0 = j2 * 2;
            *(float2*)&P_sm[seg][0][j0] = make_float2(v0a.x, v1a.x);
            *(float2*)&P_sm[seg][1][j0] = make_float2(v0a.y, v1a.y);
            *(float2*)&P_sm[seg][2][j0] = make_float2(v0b.x, v1b.x);
            *(float2*)&P_sm[seg][3][j0] = make_float2(v0b.y, v1b.y);
        }

        // store gx for step s+1 (its LDG was issued one full step ago)
        if (pf_lane && s + 1 < TT) *(float4*)&x_sm[cur ^ 1][pr][pg] = pf_next;
        pf_next = pf_next2;
        __syncthreads();

        if (tid < RR * HH) {
            float hr = ((P_sm[0][gr][gk] + P_sm[1][gr][gk])
                      + (P_sm[2][gr][gk] + P_sm[3][gr][gk]))
                     + ((P_sm[4][gr][gk] + P_sm[5][gr][gk])
                      + (P_sm[6][gr][gk] + P_sm[7][gr][gk])) + bhr;
            float hz = ((P_sm[0][gr][64 + gk] + P_sm[1][gr][64 + gk])
                      + (P_sm[2][gr][64 + gk] + P_sm[3][gr][64 + gk]))
                     + ((P_sm[4][gr][64 + gk] + P_sm[5][gr][64 + gk])
                      + (P_sm[6][gr][64 + gk] + P_sm[7][gr][64 + gk])) + bhz;
            float hn = ((P_sm[0][gr][128 + gk] + P_sm[1][gr][128 + gk])
                      + (P_sm[2][gr][128 + gk] + P_sm[3][gr][128 + gk]))
                     + ((P_sm[4][gr][128 + gk] + P_sm[5][gr][128 + gk])
                      + (P_sm[6][gr][128 + gk] + P_sm[7][gr][128 + gk])) + bhn;
            float rg = sigf(x_sm[cur][gr][gk]       + hr);
            float zg = sigf(x_sm[cur][gr][64 + gk]  + hz);
            float ng = tanh_f(x_sm[cur][gr][128 + gk] + rg * hn);
            h_reg = (1.f - zg) * ng + zg * h_reg;
            h_sm[gk * 4 + gr] = h_reg;
            if (out_seq)
                out_seq[((size_t)(b0 + gr) * TT + t) * 128 + dir * HH + gk] = h_reg;
        }
        __syncthreads();
    }

    if (hT && tid < RR * HH)
        hT[(b0 + gr) * 128 + dir * HH + gk] = h_reg;
}

// ---------------------------------------------------------------------------
// Head: LayerNorm(128) -> Linear(128->64)+ReLU -> Linear(64->11)
// ---------------------------------------------------------------------------
__global__ void __launch_bounds__(128, 4) head_kernel(
    const float* __restrict__ ln_g, const float* __restrict__ ln_b,
    const float* __restrict__ W1, const float* __restrict__ b1,
    const float* __restrict__ W2, const float* __restrict__ b2,
    float* __restrict__ out)
{
    const int b = blockIdx.x;
    const int tid = threadIdx.x;
    const int lane = tid & 31, wid = tid >> 5;

    __shared__ float y_sm[128];
    __shared__ float h_sm[HH];
    __shared__ float r1[4], r2[4];
    __shared__ float stats[2];

    float e = g_hT[b * 128 + tid];
    float s1 = e, s2 = e * e;
#pragma unroll
    for (int o = 16; o; o >>= 1) {
        s1 += __shfl_down_sync(0xffffffffu, s1, o);
        s2 += __shfl_down_sync(0xffffffffu, s2, o);
    }
    if (lane == 0) { r1[wid] = s1; r2[wid] = s2; }
    __syncthreads();
    if (tid == 0) {
        float a = r1[0] + r1[1] + r1[2] + r1[3];
        float c = r2[0] + r2[1] + r2[2] + r2[3];
        float mu = a * (1.f / 128.f);
        float var = c * (1.f / 128.f) - mu * mu;
        stats[0] = mu;
        stats[1] = rsqrtf(var + 1e-5f);
    }
    __syncthreads();
    y_sm[tid] = (e - stats[0]) * stats[1] * ln_g[tid] + ln_b[tid];
    __syncthreads();

    if (tid < HH) {
        float acc = b1[tid];
#pragma unroll
        for (int k = 0; k < 128; k++) acc += W1[tid * 128 + k] * y_sm[k];
        h_sm[tid] = fmaxf(acc, 0.f);
    }
    __syncthreads();
    if (tid < OUTD) {
        float acc = b2[tid];
#pragma unroll
        for (int k = 0; k < HH; k++) acc += W2[tid * HH + k] * h_sm[k];
        out[b * OUTD + tid] = acc;
    }
}

// ---------------------------------------------------------------------------
extern "C" void kernel_launch(void* const* d_in, const int* in_sizes, int n_in,
                              void* d_out, int out_size) {
    (void)in_sizes; (void)n_in; (void)out_size;
    const float* x     = (const float*)d_in[0];
    const float* Wih00 = (const float*)d_in[1];
    const float* Whh00 = (const float*)d_in[2];
    const float* bih00 = (const float*)d_in[3];
    const float* bhh00 = (const float*)d_in[4];
    const float* Wih01 = (const float*)d_in[5];
    const float* Whh01 = (const float*)d_in[6];
    const float* bih01 = (const float*)d_in[7];
    const float* bhh01 = (const float*)d_in[8];
    const float* Wih10 = (const float*)d_in[9];
    const float* Whh10 = (const float*)d_in[10];
    const float* bih10 = (const float*)d_in[11];
    const float* bhh10 = (const float*)d_in[12];
    const float* Wih11 = (const float*)d_in[13];
    const float* Whh11 = (const float*)d_in[14];
    const float* bih11 = (const float*)d_in[15];
    const float* bhh11 = (const float*)d_in[16];
    const float* ln_g  = (const float*)d_in[17];
    const float* ln_b  = (const float*)d_in[18];
    const float* W1    = (const float*)d_in[19];
    const float* b1    = (const float*)d_in[20];
    const float* W2    = (const float*)d_in[21];
    const float* b2    = (const float*)d_in[22];
    float* out = (float*)d_out;

    float* gx0  = nullptr; cudaGetSymbolAddress((void**)&gx0,  g_gx0);
    float* gx1  = nullptr; cudaGetSymbolAddress((void**)&gx1,  g_gx1);
    float* out0 = nullptr; cudaGetSymbolAddress((void**)&out0, g_out0);
    float* hT   = nullptr; cudaGetSymbolAddress((void**)&hT,   g_hT);
    float* Wt0  = nullptr; cudaGetSymbolAddress((void**)&Wt0,  g_Wt0);
    float* Wt1  = nullptr; cudaGetSymbolAddress((void**)&Wt1,  g_Wt1);

    const int smem32  = (32 * 128 + 32 * 64) * 4;
    const int smem128 = (128 * 128 + 128 * 64) * 4;
    cudaFuncSetAttribute(gemm_gx_kernel<32, 29>,
                         cudaFuncAttributeMaxDynamicSharedMemorySize, smem32);
    cudaFuncSetAttribute(gemm_gx_kernel<128, 128>,
                         cudaFuncAttributeMaxDynamicSharedMemorySize, smem128);

    // one-time weight transposes (tiny; graph-captured each replay, ~5us)
    transpose_w_kernel<<<(32 * NN2 + 255) / 256, 256>>>(Wih00, Wih01, Wt0, 32, INP);
    transpose_w_kernel<<<(128 * NN2 + 255) / 256, 256>>>(Wih10, Wih11, Wt1, 128, 128);

    dim3 ggrid(MT / 128, 6);
    dim3 rgrid(BB / RR, 2);

    gemm_gx_kernel<32, 29><<<ggrid, 256, smem32>>>(
        x, INP, Wt0, bih00, bih01, gx0);
    rec_kernel<<<rgrid, RBD>>>(gx0, Whh00, bhh00, Whh01, bhh01, out0, nullptr);
    gemm_gx_kernel<128, 128><<<ggrid, 256, smem128>>>(
        out0, 128, Wt1, bih10, bih11, gx1);
    rec_kernel<<<rgrid, RBD>>>(gx1, Whh10, bhh10, Whh11, bhh11, nullptr, hT);
    head_kernel<<<BB, 128>>>(ln_g, ln_b, W1, b1, W2, b2, out);
}